// round 4
// baseline (speedup 1.0000x reference)
#include <cuda_runtime.h>
#include <cstdint>

// Problem constants
#define Bq   1024
#define Nn   128
#define Dd   256
#define Hh   8
#define NB   4
#define NEGV (-1e9f)
#define CLIPV 10.0f
#define INV_SQRT_DH 0.17677669529663687f  // 1/sqrt(32)
#define INV_SQRT_D  0.0625f               // 1/sqrt(256)

// ---------------- scratch (device globals; no cudaMalloc allowed) ----------
__device__ float g_K   [Bq * Nn * Dd];   // [b][n][d]  (E@Wk)
__device__ float g_V   [Bq * Nn * Dd];   // [b][n][d]  (E@Wv)
__device__ float g_LK2 [Bq * Nn * Dd];   // [b][n][d]  (E@(Wlk@Wo^T))
__device__ float g_P   [Bq * Nn * Dd];   // [b][n][d]  (E@Ws_bot)
__device__ float g_q0  [Bq * Dd];        // step-0 query (pre-MLP)
__device__ float g_Woc [Dd * Dd];        // Wo@Wc
__device__ float g_Wlk2[Dd * Dd];        // Wlk@Wo^T
__device__ float g_WoT [Dd * Dd];        // Wo^T
__device__ float g_pc  [Dd];             // W_placeholder @ Ws
__device__ int   g_mlp;                  // 1 if (W2,b2) nonzero -> general path

// ---------------- k0: transpose Wo, detect MLP-nonzero ---------------------
__global__ void k0_prep(const float* __restrict__ Wo,
                        const float* __restrict__ W2,
                        const float* __restrict__ b2)
{
    if (blockIdx.x == 0) {
        for (int i = threadIdx.x; i < Dd * Dd; i += blockDim.x) {
            int k = i >> 8, d = i & 255;
            g_WoT[d * Dd + k] = Wo[k * Dd + d];
        }
    } else {
        __shared__ int any;
        if (threadIdx.x == 0) any = 0;
        __syncthreads();
        int loc = 0;
        for (int i = threadIdx.x; i < Dd * Dd; i += blockDim.x)
            loc |= (W2[i] != 0.0f);
        if (threadIdx.x < Dd) loc |= (b2[threadIdx.x] != 0.0f);
        if (loc) atomicOr(&any, 1);
        __syncthreads();
        if (threadIdx.x == 0) g_mlp = any;
    }
}

// ---------------- k1: Woc = Wo@Wc ; Wlk2 = Wlk@Wo^T ; pc = placeholder@Ws --
__global__ void k1_weights(const float* __restrict__ Wo,
                           const float* __restrict__ Wc,
                           const float* __restrict__ Wlk,
                           const float* __restrict__ Ws,
                           const float* __restrict__ Wph)
{
    int bid = blockIdx.x;
    int d = threadIdx.x;
    if (bid < 256) {               // Woc row bid
        float acc = 0.f;
        #pragma unroll 8
        for (int j = 0; j < Dd; j++) acc += Wo[bid * Dd + j] * Wc[j * Dd + d];
        g_Woc[bid * Dd + d] = acc;
    } else if (bid < 512) {        // Wlk2 row m
        int m = bid - 256;
        float acc = 0.f;
        #pragma unroll 8
        for (int j = 0; j < Dd; j++) acc += Wlk[m * Dd + j] * g_WoT[j * Dd + d];
        g_Wlk2[m * Dd + d] = acc;
    } else {                       // pc
        float acc = 0.f;
        #pragma unroll 8
        for (int k = 0; k < 2 * Dd; k++) acc += Wph[k] * Ws[k * Dd + d];
        g_pc[d] = acc;
    }
}

// ---------------- k2: q0 = mean_n(E) @ Wc + pc ------------------------------
__global__ void k2_q0(const float* __restrict__ E, const float* __restrict__ Wc)
{
    int b = blockIdx.x, d = threadIdx.x;
    __shared__ float g[Dd];
    float s = 0.f;
    const float* Eb = E + (size_t)b * Nn * Dd + d;
    #pragma unroll 8
    for (int n = 0; n < Nn; n++) s += Eb[n * Dd];
    g[d] = s * (1.0f / Nn);
    __syncthreads();
    float acc = g_pc[d];
    #pragma unroll 8
    for (int k = 0; k < Dd; k++) acc += g[k] * Wc[k * Dd + d];
    g_q0[b * Dd + d] = acc;
}

// ---------------- k3: big GEMMs E@{Wk,Wv,Wlk2,Ws_bot} -----------------------
// 128x128 block tile, 8x8 per thread (split 4+4), K-tile 16.
// grid: (2, 1024, 4); block 256.
__global__ void __launch_bounds__(256) k3_gemm(const float* __restrict__ E,
                                               const float* __restrict__ Wk,
                                               const float* __restrict__ Wv,
                                               const float* __restrict__ Ws)
{
    const int w = blockIdx.z;
    const float* W;
    float* out;
    if      (w == 0) { W = Wk;           out = g_K;   }
    else if (w == 1) { W = Wv;           out = g_V;   }
    else if (w == 2) { W = g_Wlk2;       out = g_LK2; }
    else             { W = Ws + Dd * Dd; out = g_P;   }

    const int rowbase = blockIdx.y * 128;
    const int colbase = blockIdx.x * 128;

    __shared__ float As[16][128];   // [k][m]
    __shared__ float Bs[16][128];   // [k][n]

    const int tid = threadIdx.x;
    const int tx = tid & 15, ty = tid >> 4;
    const int am = tid >> 1, ak0 = (tid & 1) * 8;

    float acc[8][8] = {};

    for (int kc = 0; kc < Dd; kc += 16) {
        {   // A: 128 rows x 16 k, store k-major
            const float* asrc = E + (size_t)(rowbase + am) * Dd + kc + ak0;
            float4 v0 = *(const float4*)asrc;
            float4 v1 = *(const float4*)(asrc + 4);
            As[ak0 + 0][am] = v0.x; As[ak0 + 1][am] = v0.y;
            As[ak0 + 2][am] = v0.z; As[ak0 + 3][am] = v0.w;
            As[ak0 + 4][am] = v1.x; As[ak0 + 5][am] = v1.y;
            As[ak0 + 6][am] = v1.z; As[ak0 + 7][am] = v1.w;
        }
        #pragma unroll
        for (int i = 0; i < 2; i++) {   // B: 16 k x 128 n
            int idx = tid + i * 256;
            int k = idx >> 5, n4 = idx & 31;
            *(float4*)&Bs[k][n4 * 4] =
                *(const float4*)(W + (size_t)(kc + k) * Dd + colbase + n4 * 4);
        }
        __syncthreads();
        #pragma unroll
        for (int k = 0; k < 16; k++) {
            float4 a0 = *(const float4*)&As[k][ty * 4];
            float4 a1 = *(const float4*)&As[k][64 + ty * 4];
            float4 b0 = *(const float4*)&Bs[k][tx * 4];
            float4 b1 = *(const float4*)&Bs[k][64 + tx * 4];
            float ar[8] = {a0.x, a0.y, a0.z, a0.w, a1.x, a1.y, a1.z, a1.w};
            float br[8] = {b0.x, b0.y, b0.z, b0.w, b1.x, b1.y, b1.z, b1.w};
            #pragma unroll
            for (int i = 0; i < 8; i++)
                #pragma unroll
                for (int j = 0; j < 8; j++)
                    acc[i][j] += ar[i] * br[j];
        }
        __syncthreads();
    }

    #pragma unroll
    for (int i = 0; i < 8; i++) {
        int m = rowbase + ((i < 4) ? (ty * 4 + i) : (64 + ty * 4 + i - 4));
        float4 lo = make_float4(acc[i][0], acc[i][1], acc[i][2], acc[i][3]);
        float4 hi = make_float4(acc[i][4], acc[i][5], acc[i][6], acc[i][7]);
        *(float4*)(out + (size_t)m * Dd + colbase + tx * 4)      = lo;
        *(float4*)(out + (size_t)m * Dd + colbase + 64 + tx * 4) = hi;
    }
}

// ---------------- k4: persistent decode, NB=4 batches per block -------------
struct K4Smem {
    float q[NB][Dd];          // pre-scaled query
    float heads[NB][Dd];
    float cc[NB][Nn][9];      // compat [bb][j][h]
    float pp[NB][Hh][Nn + 4]; // exp(compat) [bb][h][j]
    float ls[NB][Nn];         // logits [bb][j]
    int   list[NB][Nn];
    float er[NB][Dd];         // E-row stage (t==0) / MLP hidden
    float sum[NB][Hh];
    int   sel[NB];
    int   cnt;
};

// raw q in S.q -> apply optional residual MLP, then scale by 1/sqrt(DH)
__device__ __forceinline__ void k4_finalize_q(K4Smem& S, int tid, int mlp,
                                              const float* __restrict__ W1,
                                              const float* __restrict__ b1,
                                              const float* __restrict__ W2,
                                              const float* __restrict__ b2)
{
    if (mlp) {
        __syncthreads();
        float m1[NB];
        #pragma unroll
        for (int bb = 0; bb < NB; bb++) m1[bb] = b1[tid];
        #pragma unroll 8
        for (int k = 0; k < Dd; k++) {
            float wv = W1[k * Dd + tid];
            #pragma unroll
            for (int bb = 0; bb < NB; bb++) m1[bb] += S.q[bb][k] * wv;
        }
        #pragma unroll
        for (int bb = 0; bb < NB; bb++) S.er[bb][tid] = fmaxf(m1[bb], 0.0f);
        __syncthreads();
        float m2[NB];
        #pragma unroll
        for (int bb = 0; bb < NB; bb++) m2[bb] = b2[tid];
        #pragma unroll 8
        for (int k = 0; k < Dd; k++) {
            float wv = W2[k * Dd + tid];
            #pragma unroll
            for (int bb = 0; bb < NB; bb++) m2[bb] += S.er[bb][k] * wv;
        }
        __syncthreads();
        #pragma unroll
        for (int bb = 0; bb < NB; bb++)
            S.q[bb][tid] = (S.q[bb][tid] + m2[bb]) * INV_SQRT_DH;
    } else {
        #pragma unroll
        for (int bb = 0; bb < NB; bb++) S.q[bb][tid] *= INV_SQRT_DH;
    }
    __syncthreads();
}

__global__ void __launch_bounds__(256) k4_decode(const float* __restrict__ E,
                                                 const float* __restrict__ coords,
                                                 const float* __restrict__ Ws,
                                                 const float* __restrict__ W1,
                                                 const float* __restrict__ b1,
                                                 const float* __restrict__ W2,
                                                 const float* __restrict__ b2,
                                                 float* __restrict__ out)
{
    extern __shared__ char smem_raw[];
    K4Smem& S = *(K4Smem*)smem_raw;

    const int b0 = blockIdx.x * NB;
    const int tid = threadIdx.x;
    const int warp = tid >> 5, lane = tid & 31;
    const int mlp = g_mlp;

    if (tid < Nn) {
        #pragma unroll
        for (int bb = 0; bb < NB; bb++) S.list[bb][tid] = tid;
    }
    if (tid == 0) S.cnt = Nn;
    #pragma unroll
    for (int bb = 0; bb < NB; bb++)
        S.q[bb][tid] = g_q0[(b0 + bb) * Dd + tid];
    k4_finalize_q(S, tid, mlp, W1, b1, W2, b2);

    const float* Kbase  = g_K   + (size_t)b0 * Nn * Dd;
    const float* Vbase  = g_V   + (size_t)b0 * Nn * Dd;
    const float* LKbase = g_LK2 + (size_t)b0 * Nn * Dd;

    float ll = 0.f, cost = 0.f;         // lane0 of warps 0..NB-1
    float fx = 0.f, fy = 0.f, px = 0.f, py = 0.f;
    float fctx[NB] = {0.f, 0.f, 0.f, 0.f};

    for (int t = 0; t < Nn; t++) {
        const int cnt = S.cnt;

        // ---- compat[bb][j][h] = q_h . K_h[list[j]] ------------------------
        #pragma unroll
        for (int bb = 0; bb < NB; bb++) {
            const float4* q4 = (const float4*)S.q[bb];
            float4 qa = q4[lane], qb = q4[lane + 32];
            const float* Kb = Kbase + (size_t)bb * Nn * Dd;
            for (int j = warp; j < cnt; j += 8) {
                const float4* Kr = (const float4*)(Kb + (size_t)S.list[bb][j] * Dd);
                float4 k0 = Kr[lane], k1 = Kr[lane + 32];
                float alo = k0.x * qa.x + k0.y * qa.y + k0.z * qa.z + k0.w * qa.w;
                float ahi = k1.x * qb.x + k1.y * qb.y + k1.z * qb.z + k1.w * qb.w;
                #pragma unroll
                for (int o = 1; o < 8; o <<= 1) {
                    alo += __shfl_xor_sync(0xffffffffu, alo, o);
                    ahi += __shfl_xor_sync(0xffffffffu, ahi, o);
                }
                if ((lane & 7) == 0) {
                    int hg = lane >> 3;
                    S.cc[bb][j][hg]     = alo;
                    S.cc[bb][j][4 + hg] = ahi;
                }
            }
        }
        __syncthreads();

        // ---- softmax: warp w = head w, loop bb; exp into pp ---------------
        {
            const int h = warp;
            #pragma unroll
            for (int bb = 0; bb < NB; bb++) {
                float m = NEGV;
                for (int j = lane; j < cnt; j += 32) m = fmaxf(m, S.cc[bb][j][h]);
                #pragma unroll
                for (int o = 16; o; o >>= 1)
                    m = fmaxf(m, __shfl_xor_sync(0xffffffffu, m, o));
                float s = 0.f;
                for (int j = lane; j < cnt; j += 32) {
                    float e = expf(S.cc[bb][j][h] - m);
                    S.pp[bb][h][j] = e;
                    s += e;
                }
                #pragma unroll
                for (int o = 16; o; o >>= 1) s += __shfl_xor_sync(0xffffffffu, s, o);
                if (lane == 0) S.sum[bb][h] = s;
            }
        }
        __syncthreads();

        // ---- heads[bb][d] = (sum_j pp*V)/sum ------------------------------
        {
            const int d = tid, h = tid >> 5;
            float a[NB] = {0.f, 0.f, 0.f, 0.f};
            const float* Vd = Vbase + d;
            #pragma unroll 2
            for (int j = 0; j < cnt; j++) {
                #pragma unroll
                for (int bb = 0; bb < NB; bb++)
                    a[bb] += S.pp[bb][h][j] *
                             Vd[((size_t)bb * Nn + S.list[bb][j]) * Dd];
            }
            #pragma unroll
            for (int bb = 0; bb < NB; bb++)
                S.heads[bb][d] = a[bb] / S.sum[bb][h];
        }
        __syncthreads();

        // ---- logits[bb][j] = clip*tanh(heads . LK2[list[j]] / sqrtD) ------
        #pragma unroll
        for (int bb = 0; bb < NB; bb++) {
            const float4* h4 = (const float4*)S.heads[bb];
            float4 ha = h4[lane], hb = h4[lane + 32];
            const float* Lb = LKbase + (size_t)bb * Nn * Dd;
            for (int j = warp; j < cnt; j += 8) {
                const float4* Lr = (const float4*)(Lb + (size_t)S.list[bb][j] * Dd);
                float4 l0 = Lr[lane], l1 = Lr[lane + 32];
                float a = l0.x * ha.x + l0.y * ha.y + l0.z * ha.z + l0.w * ha.w
                        + l1.x * hb.x + l1.y * hb.y + l1.z * hb.z + l1.w * hb.w;
                #pragma unroll
                for (int o = 16; o; o >>= 1) a += __shfl_xor_sync(0xffffffffu, a, o);
                if (lane == 0) S.ls[bb][j] = CLIPV * tanhf(a * INV_SQRT_D);
            }
        }
        __syncthreads();

        // ---- argmax + log-softmax at selected (warp bb) -------------------
        if (warp < NB) {
            const int bb = warp;
            float m = NEGV; int mj = 0;
            for (int j = lane; j < cnt; j += 32) {
                float v = S.ls[bb][j];
                if (v > m) { m = v; mj = j; }
            }
            #pragma unroll
            for (int o = 16; o; o >>= 1) {
                float vm = __shfl_xor_sync(0xffffffffu, m, o);
                int   vj = __shfl_xor_sync(0xffffffffu, mj, o);
                if (vm > m || (vm == m && vj < mj)) { m = vm; mj = vj; }
            }
            float s = 0.f;
            for (int j = lane; j < cnt; j += 32) s += expf(S.ls[bb][j] - m);
            #pragma unroll
            for (int o = 16; o; o >>= 1) s += __shfl_xor_sync(0xffffffffu, s, o);
            if (lane == 0) {
                int node = S.list[bb][mj];
                S.sel[bb] = node;
                ll += S.ls[bb][mj] - (m + logf(s));
                float cx = coords[((size_t)(b0 + bb) * Nn + node) * 2 + 0];
                float cy = coords[((size_t)(b0 + bb) * Nn + node) * 2 + 1];
                if (t == 0) { fx = cx; fy = cy; }
                else {
                    float dx = cx - px, dy = cy - py;
                    cost += sqrtf(dx * dx + dy * dy);
                }
                px = cx; py = cy;
                S.list[bb][mj] = S.list[bb][cnt - 1];   // swap-remove
            }
        }
        if (tid == 0) S.cnt = cnt - 1;
        __syncthreads();

        if (t == 0) {   // fctx[bb] = E[b,first] @ Ws_top
            #pragma unroll
            for (int bb = 0; bb < NB; bb++)
                S.er[bb][tid] =
                    E[((size_t)(b0 + bb) * Nn + S.sel[bb]) * Dd + tid];
            __syncthreads();
            float f[NB] = {0.f, 0.f, 0.f, 0.f};
            #pragma unroll 8
            for (int k = 0; k < Dd; k++) {
                float wv = Ws[k * Dd + tid];
                #pragma unroll
                for (int bb = 0; bb < NB; bb++) f[bb] += S.er[bb][k] * wv;
            }
            #pragma unroll
            for (int bb = 0; bb < NB; bb++) fctx[bb] = f[bb];
            __syncthreads();
        }

        if (t < Nn - 1) {   // next raw query: heads@Woc + fctx + P[sel]
            float base[NB];
            #pragma unroll
            for (int bb = 0; bb < NB; bb++)
                base[bb] = fctx[bb] +
                    g_P[((size_t)(b0 + bb) * Nn + S.sel[bb]) * Dd + tid];
            float a[NB] = {0.f, 0.f, 0.f, 0.f};
            const float* Wp = g_Woc + tid;
            #pragma unroll 8
            for (int k = 0; k < Dd; k++) {
                float wv = Wp[(size_t)k * Dd];
                a[0] += S.heads[0][k] * wv;
                a[1] += S.heads[1][k] * wv;
                a[2] += S.heads[2][k] * wv;
                a[3] += S.heads[3][k] * wv;
            }
            __syncthreads();   // everyone done reading heads/q before q rewrite
            #pragma unroll
            for (int bb = 0; bb < NB; bb++) S.q[bb][tid] = base[bb] + a[bb];
            k4_finalize_q(S, tid, mlp, W1, b1, W2, b2);
        }
    }

    if (warp < NB && lane == 0) {
        float dx = px - fx, dy = py - fy;
        cost += sqrtf(dx * dx + dy * dy);
        out[b0 + warp]      = cost;
        out[Bq + b0 + warp] = ll;
    }
}

// ---------------- launcher ---------------------------------------------------
extern "C" void kernel_launch(void* const* d_in, const int* in_sizes, int n_in,
                              void* d_out, int out_size)
{
    const float* coords = (const float*)d_in[0];
    const float* E      = (const float*)d_in[1];
    const float* Wk     = (const float*)d_in[2];
    const float* Wv     = (const float*)d_in[3];
    const float* Wlk    = (const float*)d_in[4];
    const float* Wo     = (const float*)d_in[5];
    const float* Wc     = (const float*)d_in[6];
    const float* Ws     = (const float*)d_in[7];
    const float* Wph    = (const float*)d_in[8];
    const float* W1     = (const float*)d_in[9];
    const float* b1     = (const float*)d_in[10];
    const float* W2     = (const float*)d_in[11];
    const float* b2     = (const float*)d_in[12];
    float* out = (float*)d_out;

    const int k4_smem = (int)sizeof(K4Smem);
    cudaFuncSetAttribute(k4_decode, cudaFuncAttributeMaxDynamicSharedMemorySize,
                         k4_smem);

    k0_prep<<<2, 256>>>(Wo, W2, b2);
    k1_weights<<<513, 256>>>(Wo, Wc, Wlk, Ws, Wph);
    k2_q0<<<Bq, 256>>>(E, Wc);
    dim3 g3(2, 1024, 4);
    k3_gemm<<<g3, 256>>>(E, Wk, Wv, Ws);
    k4_decode<<<Bq / NB, 256, k4_smem>>>(E, coords, Ws, W1, b1, W2, b2, out);
}

// round 5
// speedup vs baseline: 1.7340x; 1.7340x over previous
#include <cuda_runtime.h>
#include <cstdint>

// Problem constants
#define Bq   1024
#define Nn   128
#define Dd   256
#define Hh   8
#define NB   2
#define NEGV (-1e9f)
#define CLIPV 10.0f
#define INV_SQRT_DH 0.17677669529663687f  // 1/sqrt(32)
#define INV_SQRT_D  0.0625f               // 1/sqrt(256)

// ---------------- scratch (device globals; no cudaMalloc allowed) ----------
__device__ float g_K   [Bq * Nn * Dd];   // [b][n][d]  (E@Wk)
__device__ float g_V   [Bq * Nn * Dd];   // [b][n][d]  (E@Wv)
__device__ float g_LK2 [Bq * Nn * Dd];   // [b][n][d]  (E@(Wlk@Wo^T))
__device__ float g_P   [Bq * Nn * Dd];   // [b][n][d]  (E@Ws_bot)
__device__ float g_q0  [Bq * Dd];        // step-0 query (pre-MLP)
__device__ float g_Woc [Dd * Dd];        // Wo@Wc
__device__ float g_Wlk2[Dd * Dd];        // Wlk@Wo^T
__device__ float g_WoT [Dd * Dd];        // Wo^T
__device__ float g_pc  [Dd];             // W_placeholder @ Ws
__device__ int   g_mlp;                  // 1 if (W2,b2) nonzero -> general path

// ---------------- k0: transpose Wo, detect MLP-nonzero ---------------------
__global__ void k0_prep(const float* __restrict__ Wo,
                        const float* __restrict__ W2,
                        const float* __restrict__ b2)
{
    if (blockIdx.x == 0) {
        for (int i = threadIdx.x; i < Dd * Dd; i += blockDim.x) {
            int k = i >> 8, d = i & 255;
            g_WoT[d * Dd + k] = Wo[k * Dd + d];
        }
    } else {
        __shared__ int any;
        if (threadIdx.x == 0) any = 0;
        __syncthreads();
        int loc = 0;
        for (int i = threadIdx.x; i < Dd * Dd; i += blockDim.x)
            loc |= (W2[i] != 0.0f);
        if (threadIdx.x < Dd) loc |= (b2[threadIdx.x] != 0.0f);
        if (loc) atomicOr(&any, 1);
        __syncthreads();
        if (threadIdx.x == 0) g_mlp = any;
    }
}

// ---------------- k1: Woc = Wo@Wc ; Wlk2 = Wlk@Wo^T ; pc = placeholder@Ws --
__global__ void k1_weights(const float* __restrict__ Wo,
                           const float* __restrict__ Wc,
                           const float* __restrict__ Wlk,
                           const float* __restrict__ Ws,
                           const float* __restrict__ Wph)
{
    int bid = blockIdx.x;
    int d = threadIdx.x;
    if (bid < 256) {               // Woc row bid
        float acc = 0.f;
        #pragma unroll 8
        for (int j = 0; j < Dd; j++) acc += Wo[bid * Dd + j] * Wc[j * Dd + d];
        g_Woc[bid * Dd + d] = acc;
    } else if (bid < 512) {        // Wlk2 row m
        int m = bid - 256;
        float acc = 0.f;
        #pragma unroll 8
        for (int j = 0; j < Dd; j++) acc += Wlk[m * Dd + j] * g_WoT[j * Dd + d];
        g_Wlk2[m * Dd + d] = acc;
    } else {                       // pc
        float acc = 0.f;
        #pragma unroll 8
        for (int k = 0; k < 2 * Dd; k++) acc += Wph[k] * Ws[k * Dd + d];
        g_pc[d] = acc;
    }
}

// ---------------- k2: q0 = mean_n(E) @ Wc + pc ------------------------------
__global__ void k2_q0(const float* __restrict__ E, const float* __restrict__ Wc)
{
    int b = blockIdx.x, d = threadIdx.x;
    __shared__ float g[Dd];
    float s = 0.f;
    const float* Eb = E + (size_t)b * Nn * Dd + d;
    #pragma unroll 8
    for (int n = 0; n < Nn; n++) s += Eb[n * Dd];
    g[d] = s * (1.0f / Nn);
    __syncthreads();
    float acc = g_pc[d];
    #pragma unroll 8
    for (int k = 0; k < Dd; k++) acc += g[k] * Wc[k * Dd + d];
    g_q0[b * Dd + d] = acc;
}

// ---------------- k3: big GEMMs E@{Wk,Wv,Wlk2,Ws_bot} -----------------------
// 128x128 block tile, 8x8 per thread (split 4+4), K-tile 16.
// grid: (2, 1024, 4); block 256.
__global__ void __launch_bounds__(256) k3_gemm(const float* __restrict__ E,
                                               const float* __restrict__ Wk,
                                               const float* __restrict__ Wv,
                                               const float* __restrict__ Ws)
{
    const int w = blockIdx.z;
    const float* W;
    float* out;
    if      (w == 0) { W = Wk;           out = g_K;   }
    else if (w == 1) { W = Wv;           out = g_V;   }
    else if (w == 2) { W = g_Wlk2;       out = g_LK2; }
    else             { W = Ws + Dd * Dd; out = g_P;   }

    const int rowbase = blockIdx.y * 128;
    const int colbase = blockIdx.x * 128;

    __shared__ float As[16][128];   // [k][m]
    __shared__ float Bs[16][128];   // [k][n]

    const int tid = threadIdx.x;
    const int tx = tid & 15, ty = tid >> 4;
    const int am = tid >> 1, ak0 = (tid & 1) * 8;

    float acc[8][8] = {};

    for (int kc = 0; kc < Dd; kc += 16) {
        {   // A: 128 rows x 16 k, store k-major
            const float* asrc = E + (size_t)(rowbase + am) * Dd + kc + ak0;
            float4 v0 = *(const float4*)asrc;
            float4 v1 = *(const float4*)(asrc + 4);
            As[ak0 + 0][am] = v0.x; As[ak0 + 1][am] = v0.y;
            As[ak0 + 2][am] = v0.z; As[ak0 + 3][am] = v0.w;
            As[ak0 + 4][am] = v1.x; As[ak0 + 5][am] = v1.y;
            As[ak0 + 6][am] = v1.z; As[ak0 + 7][am] = v1.w;
        }
        #pragma unroll
        for (int i = 0; i < 2; i++) {   // B: 16 k x 128 n
            int idx = tid + i * 256;
            int k = idx >> 5, n4 = idx & 31;
            *(float4*)&Bs[k][n4 * 4] =
                *(const float4*)(W + (size_t)(kc + k) * Dd + colbase + n4 * 4);
        }
        __syncthreads();
        #pragma unroll
        for (int k = 0; k < 16; k++) {
            float4 a0 = *(const float4*)&As[k][ty * 4];
            float4 a1 = *(const float4*)&As[k][64 + ty * 4];
            float4 b0 = *(const float4*)&Bs[k][tx * 4];
            float4 b1 = *(const float4*)&Bs[k][64 + tx * 4];
            float ar[8] = {a0.x, a0.y, a0.z, a0.w, a1.x, a1.y, a1.z, a1.w};
            float br[8] = {b0.x, b0.y, b0.z, b0.w, b1.x, b1.y, b1.z, b1.w};
            #pragma unroll
            for (int i = 0; i < 8; i++)
                #pragma unroll
                for (int j = 0; j < 8; j++)
                    acc[i][j] += ar[i] * br[j];
        }
        __syncthreads();
    }

    #pragma unroll
    for (int i = 0; i < 8; i++) {
        int m = rowbase + ((i < 4) ? (ty * 4 + i) : (64 + ty * 4 + i - 4));
        float4 lo = make_float4(acc[i][0], acc[i][1], acc[i][2], acc[i][3]);
        float4 hi = make_float4(acc[i][4], acc[i][5], acc[i][6], acc[i][7]);
        *(float4*)(out + (size_t)m * Dd + colbase + tx * 4)      = lo;
        *(float4*)(out + (size_t)m * Dd + colbase + 64 + tx * 4) = hi;
    }
}

// ---------------- k4: persistent decode, NB=2 batches per block -------------
struct K4Smem {
    float q[NB][Dd];          // pre-scaled query
    float heads[NB][Dd];
    float cc[NB][Nn][9];      // compat [bb][j][h]
    float pp[NB][Hh][Nn + 4]; // exp(compat) [bb][h][j]
    float ls[NB][Nn];         // logits [bb][j]
    int   list[NB][Nn];
    float er[NB][Dd];         // E-row stage (t==0) / MLP hidden
    float sum[NB][Hh];
    int   sel[NB];
    int   cnt;
};

// raw q in S.q -> apply optional residual MLP, then scale by 1/sqrt(DH)
__device__ __forceinline__ void k4_finalize_q(K4Smem& S, int tid, int mlp,
                                              const float* __restrict__ W1,
                                              const float* __restrict__ b1,
                                              const float* __restrict__ W2,
                                              const float* __restrict__ b2)
{
    if (mlp) {
        __syncthreads();
        float m1[NB];
        #pragma unroll
        for (int bb = 0; bb < NB; bb++) m1[bb] = b1[tid];
        #pragma unroll 8
        for (int k = 0; k < Dd; k++) {
            float wv = W1[k * Dd + tid];
            #pragma unroll
            for (int bb = 0; bb < NB; bb++) m1[bb] += S.q[bb][k] * wv;
        }
        #pragma unroll
        for (int bb = 0; bb < NB; bb++) S.er[bb][tid] = fmaxf(m1[bb], 0.0f);
        __syncthreads();
        float m2[NB];
        #pragma unroll
        for (int bb = 0; bb < NB; bb++) m2[bb] = b2[tid];
        #pragma unroll 8
        for (int k = 0; k < Dd; k++) {
            float wv = W2[k * Dd + tid];
            #pragma unroll
            for (int bb = 0; bb < NB; bb++) m2[bb] += S.er[bb][k] * wv;
        }
        __syncthreads();
        #pragma unroll
        for (int bb = 0; bb < NB; bb++)
            S.q[bb][tid] = (S.q[bb][tid] + m2[bb]) * INV_SQRT_DH;
    } else {
        #pragma unroll
        for (int bb = 0; bb < NB; bb++) S.q[bb][tid] *= INV_SQRT_DH;
    }
    __syncthreads();
}

__global__ void __launch_bounds__(256) k4_decode(const float* __restrict__ E,
                                                 const float* __restrict__ coords,
                                                 const float* __restrict__ Ws,
                                                 const float* __restrict__ W1,
                                                 const float* __restrict__ b1,
                                                 const float* __restrict__ W2,
                                                 const float* __restrict__ b2,
                                                 float* __restrict__ out)
{
    extern __shared__ char smem_raw[];
    K4Smem& S = *(K4Smem*)smem_raw;

    const int b0 = blockIdx.x * NB;
    const int tid = threadIdx.x;
    const int warp = tid >> 5, lane = tid & 31;
    // warp-half split for row-dot phases: warps 0-3 -> bb=0, warps 4-7 -> bb=1
    const int wb  = warp >> 2;      // batch handled by this warp
    const int wj0 = warp & 3;       // starting j, stride 4
    const int mlp = g_mlp;

    if (tid < Nn) {
        #pragma unroll
        for (int bb = 0; bb < NB; bb++) S.list[bb][tid] = tid;
    }
    if (tid == 0) S.cnt = Nn;
    #pragma unroll
    for (int bb = 0; bb < NB; bb++)
        S.q[bb][tid] = g_q0[(b0 + bb) * Dd + tid];
    k4_finalize_q(S, tid, mlp, W1, b1, W2, b2);

    const float* Kbase  = g_K   + (size_t)b0 * Nn * Dd;
    const float* Vbase  = g_V   + (size_t)b0 * Nn * Dd;
    const float* LKbase = g_LK2 + (size_t)b0 * Nn * Dd;

    float ll = 0.f, cost = 0.f;         // lane0 of warps 0..NB-1
    float fx = 0.f, fy = 0.f, px = 0.f, py = 0.f;
    float fctx[NB] = {0.f, 0.f};

    for (int t = 0; t < Nn; t++) {
        const int cnt = S.cnt;

        // ---- compat[wb][j][h] = q_h . K_h[list[j]]  (warp-half parallel) --
        {
            const float4* q4 = (const float4*)S.q[wb];
            float4 qa = q4[lane], qb = q4[lane + 32];
            const float* Kb = Kbase + (size_t)wb * Nn * Dd;
            const int* lst = S.list[wb];
            for (int j = wj0; j < cnt; j += 4) {
                const float4* Kr = (const float4*)(Kb + (size_t)lst[j] * Dd);
                float4 k0 = Kr[lane], k1 = Kr[lane + 32];
                float alo = k0.x * qa.x + k0.y * qa.y + k0.z * qa.z + k0.w * qa.w;
                float ahi = k1.x * qb.x + k1.y * qb.y + k1.z * qb.z + k1.w * qb.w;
                #pragma unroll
                for (int o = 1; o < 8; o <<= 1) {
                    alo += __shfl_xor_sync(0xffffffffu, alo, o);
                    ahi += __shfl_xor_sync(0xffffffffu, ahi, o);
                }
                if ((lane & 7) == 0) {
                    int hg = lane >> 3;
                    S.cc[wb][j][hg]     = alo;
                    S.cc[wb][j][4 + hg] = ahi;
                }
            }
        }
        __syncthreads();

        // ---- softmax: warp w = head w, loop bb; exp into pp ---------------
        {
            const int h = warp;
            #pragma unroll
            for (int bb = 0; bb < NB; bb++) {
                float m = NEGV;
                for (int j = lane; j < cnt; j += 32) m = fmaxf(m, S.cc[bb][j][h]);
                #pragma unroll
                for (int o = 16; o; o >>= 1)
                    m = fmaxf(m, __shfl_xor_sync(0xffffffffu, m, o));
                float s = 0.f;
                for (int j = lane; j < cnt; j += 32) {
                    float e = expf(S.cc[bb][j][h] - m);
                    S.pp[bb][h][j] = e;
                    s += e;
                }
                #pragma unroll
                for (int o = 16; o; o >>= 1) s += __shfl_xor_sync(0xffffffffu, s, o);
                if (lane == 0) S.sum[bb][h] = s;
            }
        }
        __syncthreads();

        // ---- heads[bb][d] = (sum_j pp*V)/sum  (both batches per thread) ---
        {
            const int d = tid, h = tid >> 5;
            float a[NB] = {0.f, 0.f};
            const float* Vd = Vbase + d;
            #pragma unroll 2
            for (int j = 0; j < cnt; j++) {
                #pragma unroll
                for (int bb = 0; bb < NB; bb++)
                    a[bb] += S.pp[bb][h][j] *
                             Vd[((size_t)bb * Nn + S.list[bb][j]) * Dd];
            }
            #pragma unroll
            for (int bb = 0; bb < NB; bb++)
                S.heads[bb][d] = a[bb] / S.sum[bb][h];
        }
        __syncthreads();

        // ---- logits[wb][j] = clip*tanh(heads . LK2[list[j]] / sqrtD) ------
        {
            const float4* h4 = (const float4*)S.heads[wb];
            float4 ha = h4[lane], hb = h4[lane + 32];
            const float* Lb = LKbase + (size_t)wb * Nn * Dd;
            const int* lst = S.list[wb];
            for (int j = wj0; j < cnt; j += 4) {
                const float4* Lr = (const float4*)(Lb + (size_t)lst[j] * Dd);
                float4 l0 = Lr[lane], l1 = Lr[lane + 32];
                float a = l0.x * ha.x + l0.y * ha.y + l0.z * ha.z + l0.w * ha.w
                        + l1.x * hb.x + l1.y * hb.y + l1.z * hb.z + l1.w * hb.w;
                #pragma unroll
                for (int o = 16; o; o >>= 1) a += __shfl_xor_sync(0xffffffffu, a, o);
                if (lane == 0) S.ls[wb][j] = CLIPV * tanhf(a * INV_SQRT_D);
            }
        }
        __syncthreads();

        // ---- argmax + log-softmax at selected (warp bb) -------------------
        if (warp < NB) {
            const int bb = warp;
            float m = NEGV; int mj = 0;
            for (int j = lane; j < cnt; j += 32) {
                float v = S.ls[bb][j];
                if (v > m) { m = v; mj = j; }
            }
            #pragma unroll
            for (int o = 16; o; o >>= 1) {
                float vm = __shfl_xor_sync(0xffffffffu, m, o);
                int   vj = __shfl_xor_sync(0xffffffffu, mj, o);
                if (vm > m || (vm == m && vj < mj)) { m = vm; mj = vj; }
            }
            float s = 0.f;
            for (int j = lane; j < cnt; j += 32) s += expf(S.ls[bb][j] - m);
            #pragma unroll
            for (int o = 16; o; o >>= 1) s += __shfl_xor_sync(0xffffffffu, s, o);
            if (lane == 0) {
                int node = S.list[bb][mj];
                S.sel[bb] = node;
                ll += S.ls[bb][mj] - (m + logf(s));
                float cx = coords[((size_t)(b0 + bb) * Nn + node) * 2 + 0];
                float cy = coords[((size_t)(b0 + bb) * Nn + node) * 2 + 1];
                if (t == 0) { fx = cx; fy = cy; }
                else {
                    float dx = cx - px, dy = cy - py;
                    cost += sqrtf(dx * dx + dy * dy);
                }
                px = cx; py = cy;
                S.list[bb][mj] = S.list[bb][cnt - 1];   // swap-remove
            }
        }
        if (tid == 0) S.cnt = cnt - 1;
        __syncthreads();

        if (t == 0) {   // fctx[bb] = E[b,first] @ Ws_top
            #pragma unroll
            for (int bb = 0; bb < NB; bb++)
                S.er[bb][tid] =
                    E[((size_t)(b0 + bb) * Nn + S.sel[bb]) * Dd + tid];
            __syncthreads();
            float f[NB] = {0.f, 0.f};
            #pragma unroll 8
            for (int k = 0; k < Dd; k++) {
                float wv = Ws[k * Dd + tid];
                #pragma unroll
                for (int bb = 0; bb < NB; bb++) f[bb] += S.er[bb][k] * wv;
            }
            #pragma unroll
            for (int bb = 0; bb < NB; bb++) fctx[bb] = f[bb];
            __syncthreads();
        }

        if (t < Nn - 1) {   // next raw query: heads@Woc + fctx + P[sel]
            float base[NB];
            #pragma unroll
            for (int bb = 0; bb < NB; bb++)
                base[bb] = fctx[bb] +
                    g_P[((size_t)(b0 + bb) * Nn + S.sel[bb]) * Dd + tid];
            float a0 = 0.f, a1 = 0.f, b0a = 0.f, b1a = 0.f;
            const float* Wp = g_Woc + tid;
            #pragma unroll 8
            for (int k = 0; k < Dd; k += 2) {
                float wv0 = Wp[(size_t)k * Dd];
                float wv1 = Wp[(size_t)(k + 1) * Dd];
                a0  += S.heads[0][k]     * wv0;
                b0a += S.heads[1][k]     * wv0;
                a1  += S.heads[0][k + 1] * wv1;
                b1a += S.heads[1][k + 1] * wv1;
            }
            __syncthreads();   // everyone done reading heads/q before q rewrite
            S.q[0][tid] = base[0] + (a0 + a1);
            S.q[1][tid] = base[1] + (b0a + b1a);
            k4_finalize_q(S, tid, mlp, W1, b1, W2, b2);
        }
    }

    if (warp < NB && lane == 0) {
        float dx = px - fx, dy = py - fy;
        cost += sqrtf(dx * dx + dy * dy);
        out[b0 + warp]      = cost;
        out[Bq + b0 + warp] = ll;
    }
}

// ---------------- launcher ---------------------------------------------------
extern "C" void kernel_launch(void* const* d_in, const int* in_sizes, int n_in,
                              void* d_out, int out_size)
{
    const float* coords = (const float*)d_in[0];
    const float* E      = (const float*)d_in[1];
    const float* Wk     = (const float*)d_in[2];
    const float* Wv     = (const float*)d_in[3];
    const float* Wlk    = (const float*)d_in[4];
    const float* Wo     = (const float*)d_in[5];
    const float* Wc     = (const float*)d_in[6];
    const float* Ws     = (const float*)d_in[7];
    const float* Wph    = (const float*)d_in[8];
    const float* W1     = (const float*)d_in[9];
    const float* b1     = (const float*)d_in[10];
    const float* W2     = (const float*)d_in[11];
    const float* b2     = (const float*)d_in[12];
    float* out = (float*)d_out;

    const int k4_smem = (int)sizeof(K4Smem);
    cudaFuncSetAttribute(k4_decode, cudaFuncAttributeMaxDynamicSharedMemorySize,
                         k4_smem);

    k0_prep<<<2, 256>>>(Wo, W2, b2);
    k1_weights<<<513, 256>>>(Wo, Wc, Wlk, Ws, Wph);
    k2_q0<<<Bq, 256>>>(E, Wc);
    dim3 g3(2, 1024, 4);
    k3_gemm<<<g3, 256>>>(E, Wk, Wv, Ws);
    k4_decode<<<Bq / NB, 256, k4_smem>>>(E, coords, Ws, W1, b1, W2, b2, out);
}

// round 6
// speedup vs baseline: 1.7546x; 1.0119x over previous
#include <cuda_runtime.h>
#include <cstdint>

// Problem constants
#define Bq   1024
#define Nn   128
#define Dd   256
#define Hh   8
#define NB   2
#define NEGV (-1e9f)
#define CLIPV 10.0f
#define INV_SQRT_DH 0.17677669529663687f  // 1/sqrt(32)
#define INV_SQRT_D  0.0625f               // 1/sqrt(256)

// ---------------- scratch (device globals; no cudaMalloc allowed) ----------
__device__ float g_K   [Bq * Nn * Dd];   // [b][n][d]  (E@Wk)
__device__ float g_V   [Bq * Nn * Dd];   // [b][n][d]  (E@Wv)
__device__ float g_LK2 [Bq * Nn * Dd];   // [b][n][d]  (E@(Wlk@Wo^T))
__device__ float g_P   [Bq * Nn * Dd];   // [b][n][d]  (E@Ws_bot)
__device__ float g_q0  [Bq * Dd];        // step-0 query (pre-MLP)
__device__ float g_Woc [Dd * Dd];        // Wo@Wc
__device__ float g_Wlk2[Dd * Dd];        // Wlk@Wo^T
__device__ float g_WoT [Dd * Dd];        // Wo^T
__device__ float g_pc  [Dd];             // W_placeholder @ Ws
__device__ int   g_mlp;                  // 1 if (W2,b2) nonzero -> general path

// ---------------- k0: transpose Wo, detect MLP-nonzero ---------------------
__global__ void k0_prep(const float* __restrict__ Wo,
                        const float* __restrict__ W2,
                        const float* __restrict__ b2)
{
    if (blockIdx.x == 0) {
        for (int i = threadIdx.x; i < Dd * Dd; i += blockDim.x) {
            int k = i >> 8, d = i & 255;
            g_WoT[d * Dd + k] = Wo[k * Dd + d];
        }
    } else {
        __shared__ int any;
        if (threadIdx.x == 0) any = 0;
        __syncthreads();
        int loc = 0;
        for (int i = threadIdx.x; i < Dd * Dd; i += blockDim.x)
            loc |= (W2[i] != 0.0f);
        if (threadIdx.x < Dd) loc |= (b2[threadIdx.x] != 0.0f);
        if (loc) atomicOr(&any, 1);
        __syncthreads();
        if (threadIdx.x == 0) g_mlp = any;
    }
}

// ---------------- k1: Woc = Wo@Wc ; Wlk2 = Wlk@Wo^T ; pc = placeholder@Ws --
__global__ void k1_weights(const float* __restrict__ Wo,
                           const float* __restrict__ Wc,
                           const float* __restrict__ Wlk,
                           const float* __restrict__ Ws,
                           const float* __restrict__ Wph)
{
    int bid = blockIdx.x;
    int d = threadIdx.x;
    if (bid < 256) {               // Woc row bid
        float acc = 0.f;
        #pragma unroll 8
        for (int j = 0; j < Dd; j++) acc += Wo[bid * Dd + j] * Wc[j * Dd + d];
        g_Woc[bid * Dd + d] = acc;
    } else if (bid < 512) {        // Wlk2 row m
        int m = bid - 256;
        float acc = 0.f;
        #pragma unroll 8
        for (int j = 0; j < Dd; j++) acc += Wlk[m * Dd + j] * g_WoT[j * Dd + d];
        g_Wlk2[m * Dd + d] = acc;
    } else {                       // pc
        float acc = 0.f;
        #pragma unroll 8
        for (int k = 0; k < 2 * Dd; k++) acc += Wph[k] * Ws[k * Dd + d];
        g_pc[d] = acc;
    }
}

// ---------------- k2: q0 = mean_n(E) @ Wc + pc ------------------------------
__global__ void k2_q0(const float* __restrict__ E, const float* __restrict__ Wc)
{
    int b = blockIdx.x, d = threadIdx.x;
    __shared__ float g[Dd];
    float s = 0.f;
    const float* Eb = E + (size_t)b * Nn * Dd + d;
    #pragma unroll 8
    for (int n = 0; n < Nn; n++) s += Eb[n * Dd];
    g[d] = s * (1.0f / Nn);
    __syncthreads();
    float acc = g_pc[d];
    #pragma unroll 8
    for (int k = 0; k < Dd; k++) acc += g[k] * Wc[k * Dd + d];
    g_q0[b * Dd + d] = acc;
}

// ---------------- k3: big GEMMs E@{Wk,Wv,Wlk2,Ws_bot} -----------------------
// 128x128 block tile, 8x8 per thread (split 4+4), K-tile 16.
// Register double-buffer on the GMEM tile loads to overlap with FMA work.
// grid: (2, 1024, 4); block 256.
__global__ void __launch_bounds__(256) k3_gemm(const float* __restrict__ E,
                                               const float* __restrict__ Wk,
                                               const float* __restrict__ Wv,
                                               const float* __restrict__ Ws)
{
    const int w = blockIdx.z;
    const float* W;
    float* out;
    if      (w == 0) { W = Wk;           out = g_K;   }
    else if (w == 1) { W = Wv;           out = g_V;   }
    else if (w == 2) { W = g_Wlk2;       out = g_LK2; }
    else             { W = Ws + Dd * Dd; out = g_P;   }

    const int rowbase = blockIdx.y * 128;
    const int colbase = blockIdx.x * 128;

    __shared__ float As[16][128];   // [k][m]
    __shared__ float Bs[16][128];   // [k][n]

    const int tid = threadIdx.x;
    const int tx = tid & 15, ty = tid >> 4;
    const int am = tid >> 1, ak0 = (tid & 1) * 8;
    const int bk = tid >> 5, bn4 = tid & 31;        // B: 8 k-rows per pass, 2 passes

    float acc[8][8] = {};

    // prefetch kc=0
    float4 pa0, pa1, pb0, pb1;
    {
        const float* asrc = E + (size_t)(rowbase + am) * Dd + ak0;
        pa0 = *(const float4*)asrc;
        pa1 = *(const float4*)(asrc + 4);
        pb0 = *(const float4*)(W + (size_t)bk * Dd + colbase + bn4 * 4);
        pb1 = *(const float4*)(W + (size_t)(bk + 8) * Dd + colbase + bn4 * 4);
    }

    for (int kc = 0; kc < Dd; kc += 16) {
        // commit prefetched tile to smem
        As[ak0 + 0][am] = pa0.x; As[ak0 + 1][am] = pa0.y;
        As[ak0 + 2][am] = pa0.z; As[ak0 + 3][am] = pa0.w;
        As[ak0 + 4][am] = pa1.x; As[ak0 + 5][am] = pa1.y;
        As[ak0 + 6][am] = pa1.z; As[ak0 + 7][am] = pa1.w;
        *(float4*)&Bs[bk][bn4 * 4]     = pb0;
        *(float4*)&Bs[bk + 8][bn4 * 4] = pb1;
        __syncthreads();

        // prefetch next tile while computing this one
        if (kc + 16 < Dd) {
            const float* asrc = E + (size_t)(rowbase + am) * Dd + kc + 16 + ak0;
            pa0 = *(const float4*)asrc;
            pa1 = *(const float4*)(asrc + 4);
            pb0 = *(const float4*)(W + (size_t)(kc + 16 + bk) * Dd + colbase + bn4 * 4);
            pb1 = *(const float4*)(W + (size_t)(kc + 24 + bk) * Dd + colbase + bn4 * 4);
        }

        #pragma unroll
        for (int k = 0; k < 16; k++) {
            float4 a0 = *(const float4*)&As[k][ty * 4];
            float4 a1 = *(const float4*)&As[k][64 + ty * 4];
            float4 b0 = *(const float4*)&Bs[k][tx * 4];
            float4 b1 = *(const float4*)&Bs[k][64 + tx * 4];
            float ar[8] = {a0.x, a0.y, a0.z, a0.w, a1.x, a1.y, a1.z, a1.w};
            float br[8] = {b0.x, b0.y, b0.z, b0.w, b1.x, b1.y, b1.z, b1.w};
            #pragma unroll
            for (int i = 0; i < 8; i++)
                #pragma unroll
                for (int j = 0; j < 8; j++)
                    acc[i][j] += ar[i] * br[j];
        }
        __syncthreads();
    }

    #pragma unroll
    for (int i = 0; i < 8; i++) {
        int m = rowbase + ((i < 4) ? (ty * 4 + i) : (64 + ty * 4 + i - 4));
        float4 lo = make_float4(acc[i][0], acc[i][1], acc[i][2], acc[i][3]);
        float4 hi = make_float4(acc[i][4], acc[i][5], acc[i][6], acc[i][7]);
        *(float4*)(out + (size_t)m * Dd + colbase + tx * 4)      = lo;
        *(float4*)(out + (size_t)m * Dd + colbase + 64 + tx * 4) = hi;
    }
}

// ---------------- k4: persistent decode, NB=2 batches per block -------------
struct K4Smem {
    float q[NB][Dd];          // pre-scaled query
    float heads[NB][Dd];
    float cc[NB][Nn][9];      // compat [bb][j][h]
    float pp[NB][Hh][Nn + 4]; // exp(compat) [bb][h][j]
    float ls[NB][Nn];         // logits [bb][j]
    int   list[NB][Nn];
    float er[NB][Dd];         // E-row stage (t==0) / MLP hidden
    float sum[NB][Hh];
    int   sel[NB];
    int   cnt;
};

// raw q in S.q -> apply optional residual MLP, then scale by 1/sqrt(DH)
__device__ __forceinline__ void k4_finalize_q(K4Smem& S, int tid, int mlp,
                                              const float* __restrict__ W1,
                                              const float* __restrict__ b1,
                                              const float* __restrict__ W2,
                                              const float* __restrict__ b2)
{
    if (mlp) {
        __syncthreads();
        float m1[NB];
        #pragma unroll
        for (int bb = 0; bb < NB; bb++) m1[bb] = b1[tid];
        #pragma unroll 8
        for (int k = 0; k < Dd; k++) {
            float wv = W1[k * Dd + tid];
            #pragma unroll
            for (int bb = 0; bb < NB; bb++) m1[bb] += S.q[bb][k] * wv;
        }
        #pragma unroll
        for (int bb = 0; bb < NB; bb++) S.er[bb][tid] = fmaxf(m1[bb], 0.0f);
        __syncthreads();
        float m2[NB];
        #pragma unroll
        for (int bb = 0; bb < NB; bb++) m2[bb] = b2[tid];
        #pragma unroll 8
        for (int k = 0; k < Dd; k++) {
            float wv = W2[k * Dd + tid];
            #pragma unroll
            for (int bb = 0; bb < NB; bb++) m2[bb] += S.er[bb][k] * wv;
        }
        __syncthreads();
        #pragma unroll
        for (int bb = 0; bb < NB; bb++)
            S.q[bb][tid] = (S.q[bb][tid] + m2[bb]) * INV_SQRT_DH;
    } else {
        #pragma unroll
        for (int bb = 0; bb < NB; bb++) S.q[bb][tid] *= INV_SQRT_DH;
    }
    __syncthreads();
}

__global__ void __launch_bounds__(256, 4) k4_decode(const float* __restrict__ E,
                                                    const float* __restrict__ coords,
                                                    const float* __restrict__ Ws,
                                                    const float* __restrict__ W1,
                                                    const float* __restrict__ b1,
                                                    const float* __restrict__ W2,
                                                    const float* __restrict__ b2,
                                                    float* __restrict__ out)
{
    extern __shared__ char smem_raw[];
    K4Smem& S = *(K4Smem*)smem_raw;

    const int b0 = blockIdx.x * NB;
    const int tid = threadIdx.x;
    const int warp = tid >> 5, lane = tid & 31;
    // warp-half split for row-dot phases: warps 0-3 -> bb=0, warps 4-7 -> bb=1
    const int wb  = warp >> 2;      // batch handled by this warp
    const int wj0 = warp & 3;       // starting j, stride 4
    const int mlp = g_mlp;

    if (tid < Nn) {
        #pragma unroll
        for (int bb = 0; bb < NB; bb++) S.list[bb][tid] = tid;
    }
    if (tid == 0) S.cnt = Nn;
    #pragma unroll
    for (int bb = 0; bb < NB; bb++)
        S.q[bb][tid] = g_q0[(b0 + bb) * Dd + tid];
    k4_finalize_q(S, tid, mlp, W1, b1, W2, b2);

    const float* Kbase  = g_K   + (size_t)b0 * Nn * Dd;
    const float* Vbase  = g_V   + (size_t)b0 * Nn * Dd;
    const float* LKbase = g_LK2 + (size_t)b0 * Nn * Dd;

    float ll = 0.f, cost = 0.f;         // lane0 of warps 0..NB-1
    float fx = 0.f, fy = 0.f, px = 0.f, py = 0.f;
    float fctx[NB] = {0.f, 0.f};

    for (int t = 0; t < Nn; t++) {
        const int cnt = S.cnt;

        // ---- compat[wb][j][h] = q_h . K_h[list[j]]  (warp-half parallel) --
        {
            const float4* q4 = (const float4*)S.q[wb];
            float4 qa = q4[lane], qb = q4[lane + 32];
            const float* Kb = Kbase + (size_t)wb * Nn * Dd;
            const int* lst = S.list[wb];
            for (int j = wj0; j < cnt; j += 4) {
                const float4* Kr = (const float4*)(Kb + (size_t)lst[j] * Dd);
                float4 k0 = __ldcg(Kr + lane);
                float4 k1 = __ldcg(Kr + lane + 32);
                float alo = k0.x * qa.x + k0.y * qa.y + k0.z * qa.z + k0.w * qa.w;
                float ahi = k1.x * qb.x + k1.y * qb.y + k1.z * qb.z + k1.w * qb.w;
                #pragma unroll
                for (int o = 1; o < 8; o <<= 1) {
                    alo += __shfl_xor_sync(0xffffffffu, alo, o);
                    ahi += __shfl_xor_sync(0xffffffffu, ahi, o);
                }
                if ((lane & 7) == 0) {
                    int hg = lane >> 3;
                    S.cc[wb][j][hg]     = alo;
                    S.cc[wb][j][4 + hg] = ahi;
                }
            }
        }
        __syncthreads();

        // ---- softmax: warp w = head w, loop bb; exp into pp ---------------
        {
            const int h = warp;
            #pragma unroll
            for (int bb = 0; bb < NB; bb++) {
                float m = NEGV;
                for (int j = lane; j < cnt; j += 32) m = fmaxf(m, S.cc[bb][j][h]);
                #pragma unroll
                for (int o = 16; o; o >>= 1)
                    m = fmaxf(m, __shfl_xor_sync(0xffffffffu, m, o));
                float s = 0.f;
                for (int j = lane; j < cnt; j += 32) {
                    float e = expf(S.cc[bb][j][h] - m);
                    S.pp[bb][h][j] = e;
                    s += e;
                }
                #pragma unroll
                for (int o = 16; o; o >>= 1) s += __shfl_xor_sync(0xffffffffu, s, o);
                if (lane == 0) S.sum[bb][h] = s;
            }
        }
        __syncthreads();

        // ---- heads[bb][d] = (sum_j pp*V)/sum  (both batches per thread) ---
        {
            const int d = tid, h = tid >> 5;
            float a[NB] = {0.f, 0.f};
            const float* Vd = Vbase + d;
            #pragma unroll 2
            for (int j = 0; j < cnt; j++) {
                #pragma unroll
                for (int bb = 0; bb < NB; bb++)
                    a[bb] += S.pp[bb][h][j] *
                             __ldcg(Vd + ((size_t)bb * Nn + S.list[bb][j]) * Dd);
            }
            #pragma unroll
            for (int bb = 0; bb < NB; bb++)
                S.heads[bb][d] = a[bb] / S.sum[bb][h];
        }
        __syncthreads();

        // ---- logits[wb][j] = clip*tanh(heads . LK2[list[j]] / sqrtD) ------
        {
            const float4* h4 = (const float4*)S.heads[wb];
            float4 ha = h4[lane], hb = h4[lane + 32];
            const float* Lb = LKbase + (size_t)wb * Nn * Dd;
            const int* lst = S.list[wb];
            for (int j = wj0; j < cnt; j += 4) {
                const float4* Lr = (const float4*)(Lb + (size_t)lst[j] * Dd);
                float4 l0 = __ldcg(Lr + lane);
                float4 l1 = __ldcg(Lr + lane + 32);
                float a = l0.x * ha.x + l0.y * ha.y + l0.z * ha.z + l0.w * ha.w
                        + l1.x * hb.x + l1.y * hb.y + l1.z * hb.z + l1.w * hb.w;
                #pragma unroll
                for (int o = 16; o; o >>= 1) a += __shfl_xor_sync(0xffffffffu, a, o);
                if (lane == 0) S.ls[wb][j] = CLIPV * tanhf(a * INV_SQRT_D);
            }
        }
        __syncthreads();

        // ---- argmax + log-softmax at selected (warp bb) -------------------
        if (warp < NB) {
            const int bb = warp;
            float m = NEGV; int mj = 0;
            for (int j = lane; j < cnt; j += 32) {
                float v = S.ls[bb][j];
                if (v > m) { m = v; mj = j; }
            }
            #pragma unroll
            for (int o = 16; o; o >>= 1) {
                float vm = __shfl_xor_sync(0xffffffffu, m, o);
                int   vj = __shfl_xor_sync(0xffffffffu, mj, o);
                if (vm > m || (vm == m && vj < mj)) { m = vm; mj = vj; }
            }
            float s = 0.f;
            for (int j = lane; j < cnt; j += 32) s += expf(S.ls[bb][j] - m);
            #pragma unroll
            for (int o = 16; o; o >>= 1) s += __shfl_xor_sync(0xffffffffu, s, o);
            if (lane == 0) {
                int node = S.list[bb][mj];
                S.sel[bb] = node;
                ll += S.ls[bb][mj] - (m + logf(s));
                float cx = coords[((size_t)(b0 + bb) * Nn + node) * 2 + 0];
                float cy = coords[((size_t)(b0 + bb) * Nn + node) * 2 + 1];
                if (t == 0) { fx = cx; fy = cy; }
                else {
                    float dx = cx - px, dy = cy - py;
                    cost += sqrtf(dx * dx + dy * dy);
                }
                px = cx; py = cy;
                S.list[bb][mj] = S.list[bb][cnt - 1];   // swap-remove
            }
        }
        if (tid == 0) S.cnt = cnt - 1;
        __syncthreads();

        if (t == 0) {   // fctx[bb] = E[b,first] @ Ws_top
            #pragma unroll
            for (int bb = 0; bb < NB; bb++)
                S.er[bb][tid] =
                    E[((size_t)(b0 + bb) * Nn + S.sel[bb]) * Dd + tid];
            __syncthreads();
            float f[NB] = {0.f, 0.f};
            #pragma unroll 8
            for (int k = 0; k < Dd; k++) {
                float wv = Ws[k * Dd + tid];
                #pragma unroll
                for (int bb = 0; bb < NB; bb++) f[bb] += S.er[bb][k] * wv;
            }
            #pragma unroll
            for (int bb = 0; bb < NB; bb++) fctx[bb] = f[bb];
            __syncthreads();
        }

        if (t < Nn - 1) {   // next raw query: heads@Woc + fctx + P[sel]
            float base[NB];
            #pragma unroll
            for (int bb = 0; bb < NB; bb++)
                base[bb] = fctx[bb] +
                    __ldcg(&g_P[((size_t)(b0 + bb) * Nn + S.sel[bb]) * Dd + tid]);
            float a0 = 0.f, a1 = 0.f, b0a = 0.f, b1a = 0.f;
            const float* Wp = g_Woc + tid;
            #pragma unroll 8
            for (int k = 0; k < Dd; k += 2) {
                float wv0 = Wp[(size_t)k * Dd];
                float wv1 = Wp[(size_t)(k + 1) * Dd];
                a0  += S.heads[0][k]     * wv0;
                b0a += S.heads[1][k]     * wv0;
                a1  += S.heads[0][k + 1] * wv1;
                b1a += S.heads[1][k + 1] * wv1;
            }
            __syncthreads();   // everyone done reading heads/q before q rewrite
            S.q[0][tid] = base[0] + (a0 + a1);
            S.q[1][tid] = base[1] + (b0a + b1a);
            k4_finalize_q(S, tid, mlp, W1, b1, W2, b2);
        }
    }

    if (warp < NB && lane == 0) {
        float dx = px - fx, dy = py - fy;
        cost += sqrtf(dx * dx + dy * dy);
        out[b0 + warp]      = cost;
        out[Bq + b0 + warp] = ll;
    }
}

// ---------------- launcher ---------------------------------------------------
extern "C" void kernel_launch(void* const* d_in, const int* in_sizes, int n_in,
                              void* d_out, int out_size)
{
    const float* coords = (const float*)d_in[0];
    const float* E      = (const float*)d_in[1];
    const float* Wk     = (const float*)d_in[2];
    const float* Wv     = (const float*)d_in[3];
    const float* Wlk    = (const float*)d_in[4];
    const float* Wo     = (const float*)d_in[5];
    const float* Wc     = (const float*)d_in[6];
    const float* Ws     = (const float*)d_in[7];
    const float* Wph    = (const float*)d_in[8];
    const float* W1     = (const float*)d_in[9];
    const float* b1     = (const float*)d_in[10];
    const float* W2     = (const float*)d_in[11];
    const float* b2     = (const float*)d_in[12];
    float* out = (float*)d_out;

    const int k4_smem = (int)sizeof(K4Smem);
    cudaFuncSetAttribute(k4_decode, cudaFuncAttributeMaxDynamicSharedMemorySize,
                         k4_smem);

    k0_prep<<<2, 256>>>(Wo, W2, b2);
    k1_weights<<<513, 256>>>(Wo, Wc, Wlk, Ws, Wph);
    k2_q0<<<Bq, 256>>>(E, Wc);
    dim3 g3(2, 1024, 4);
    k3_gemm<<<g3, 256>>>(E, Wk, Wv, Ws);
    k4_decode<<<Bq / NB, 256, k4_smem>>>(E, coords, Ws, W1, b1, W2, b2, out);
}